// round 1
// baseline (speedup 1.0000x reference)
#include <cuda_runtime.h>
#include <cuda_bf16.h>

// out[row, :] = W[days[row], :] + bias, row in [0, B*T), D=1024 floats.
// D/4 = 256 float4 per row -> one CTA per row, one float4 per thread.
static constexpr int D4 = 256;  // 1024 / 4

__global__ void __launch_bounds__(256, 8)
doy_gather_kernel(const int* __restrict__ days,
                  const float4* __restrict__ W4,
                  const float4* __restrict__ b4,
                  float4* __restrict__ out4)
{
    const int row = blockIdx.x;       // 0 .. B*T-1
    const int d4  = threadIdx.x;      // 0 .. 255

    const int day = __ldg(days + row);          // broadcast within CTA (L1 hit)
    const float4 w = __ldg(W4 + (size_t)day * D4 + d4);  // L2-resident (1.5MB table)
    const float4 b = __ldg(b4 + d4);

    float4 r;
    r.x = w.x + b.x;
    r.y = w.y + b.y;
    r.z = w.z + b.z;
    r.w = w.w + b.w;

    // Streaming store: output (537MB) is write-once, keep it out of L2
    __stcs(out4 + (size_t)row * D4 + d4, r);
}

extern "C" void kernel_launch(void* const* d_in, const int* in_sizes, int n_in,
                              void* d_out, int out_size)
{
    // metadata order: days_of_year [B,T] int32, W [365,D] fp32, b [D] fp32
    const int*    days = (const int*)d_in[0];
    const float4* W4   = (const float4*)d_in[1];
    const float4* b4   = (const float4*)d_in[2];
    float4*       out4 = (float4*)d_out;

    const int n_rows = in_sizes[0];   // B*T = 131072

    doy_gather_kernel<<<n_rows, 256>>>(days, W4, b4, out4);
}

// round 2
// speedup vs baseline: 1.1629x; 1.1629x over previous
#include <cuda_runtime.h>
#include <cuda_bf16.h>

// out[row, :] = W[days[row], :] + bias, D = 1024 floats = 256 float4.
// One CTA of 256 threads handles ROWS_PER_CTA rows; each thread owns one
// float4 column across all 8 rows -> bias loaded once, 8-deep MLP on the
// gather/store stream.
static constexpr int D4 = 256;          // 1024 / 4
static constexpr int ROWS_PER_CTA = 8;

__global__ void __launch_bounds__(256, 4)
doy_gather8_kernel(const int* __restrict__ days,
                   const float4* __restrict__ W4,
                   const float4* __restrict__ b4,
                   float4* __restrict__ out4,
                   int n_rows)
{
    const int d4   = threadIdx.x;                 // column (float4 index)
    const int row0 = blockIdx.x * ROWS_PER_CTA;

    const float4 b = __ldg(b4 + d4);              // once per thread

    // Broadcast index loads (same addr across the CTA -> L1 broadcast)
    int day[ROWS_PER_CTA];
#pragma unroll
    for (int r = 0; r < ROWS_PER_CTA; ++r)
        day[r] = __ldg(days + row0 + r);

    // 8 independent gathers from the L2-resident 1.5MB table
    float4 w[ROWS_PER_CTA];
#pragma unroll
    for (int r = 0; r < ROWS_PER_CTA; ++r)
        w[r] = __ldg(W4 + (size_t)day[r] * D4 + d4);

#pragma unroll
    for (int r = 0; r < ROWS_PER_CTA; ++r) {
        float4 v;
        v.x = w[r].x + b.x;
        v.y = w[r].y + b.y;
        v.z = w[r].z + b.z;
        v.w = w[r].w + b.w;
        // streaming store: 537MB write-once stream, keep it out of L2
        __stcs(out4 + (size_t)(row0 + r) * D4 + d4, v);
    }
}

extern "C" void kernel_launch(void* const* d_in, const int* in_sizes, int n_in,
                              void* d_out, int out_size)
{
    const int*    days = (const int*)d_in[0];
    const float4* W4   = (const float4*)d_in[1];
    const float4* b4   = (const float4*)d_in[2];
    float4*       out4 = (float4*)d_out;

    const int n_rows = in_sizes[0];                 // B*T = 131072 (divisible by 8)
    const int n_cta  = n_rows / ROWS_PER_CTA;       // 16384

    doy_gather8_kernel<<<n_cta, 256>>>(days, W4, b4, out4, n_rows);
}